// round 3
// baseline (speedup 1.0000x reference)
#include <cuda_runtime.h>
#include <cstdint>

#define TOKENS 16384
#define DIM    4096
#define NTHREADS 512
#define NWARPS  (NTHREADS / 32)       // 16
#define PER_THREAD (DIM / NTHREADS)   // 8
#define ROWS_PER_BLOCK 8
#define INPUT_SCALE 0.01f
#define EPS 1e-5f

// Each block processes ROWS_PER_BLOCK consecutive rows, software-pipelined:
// row k+1's global loads are issued BEFORE row k's barrier, so DRAM latency
// hides under the barrier + epilogue. Warp partials double-buffered so one
// barrier per row suffices.
__global__ __launch_bounds__(NTHREADS, 2)
void dq_add_ln_q_kernel(const float* __restrict__ res,
                        const int*   __restrict__ qin,
                        const float* __restrict__ w,
                        const float* __restrict__ bias,
                        float* __restrict__ x_out,
                        float* __restrict__ qf_out,
                        int8_t* __restrict__ q8_out,
                        int q_mode) {
    __shared__ float2 part[2][NWARPS];

    const int tid  = threadIdx.x;
    const int lane = tid & 31;
    const int wid  = tid >> 5;
    const int col  = tid * PER_THREAD;
    long base = (long)blockIdx.x * ROWS_PER_BLOCK * DIM + col;

    // Affine params: load once per block (reused for all 8 rows).
    const float4 w0 = __ldg(reinterpret_cast<const float4*>(w    + col));
    const float4 w1 = __ldg(reinterpret_cast<const float4*>(w    + col) + 1);
    const float4 b0 = __ldg(reinterpret_cast<const float4*>(bias + col));
    const float4 b1 = __ldg(reinterpret_cast<const float4*>(bias + col) + 1);

    const float inv_d = 1.0f / (float)DIM;

    // Prologue: load row 0.
    float4 r0 = __ldcs(reinterpret_cast<const float4*>(res + base));
    float4 r1 = __ldcs(reinterpret_cast<const float4*>(res + base) + 1);
    int4   i0 = __ldcs(reinterpret_cast<const int4*>(qin + base));
    int4   i1 = __ldcs(reinterpret_cast<const int4*>(qin + base) + 1);

    #pragma unroll
    for (int k = 0; k < ROWS_PER_BLOCK; ++k) {
        float v[PER_THREAD];
        v[0] = fmaf((float)i0.x, INPUT_SCALE, r0.x);
        v[1] = fmaf((float)i0.y, INPUT_SCALE, r0.y);
        v[2] = fmaf((float)i0.z, INPUT_SCALE, r0.z);
        v[3] = fmaf((float)i0.w, INPUT_SCALE, r0.w);
        v[4] = fmaf((float)i1.x, INPUT_SCALE, r1.x);
        v[5] = fmaf((float)i1.y, INPUT_SCALE, r1.y);
        v[6] = fmaf((float)i1.z, INPUT_SCALE, r1.z);
        v[7] = fmaf((float)i1.w, INPUT_SCALE, r1.w);

        // Residual store: fire-and-forget, overlaps everything below.
        __stcs(reinterpret_cast<float4*>(x_out + base),
               make_float4(v[0], v[1], v[2], v[3]));
        __stcs(reinterpret_cast<float4*>(x_out + base) + 1,
               make_float4(v[4], v[5], v[6], v[7]));

        float s = 0.0f, ss = 0.0f;
        #pragma unroll
        for (int j = 0; j < PER_THREAD; ++j) {
            s  += v[j];
            ss = fmaf(v[j], v[j], ss);
        }
        #pragma unroll
        for (int off = 16; off > 0; off >>= 1) {
            s  += __shfl_down_sync(0xFFFFFFFFu, s,  off);
            ss += __shfl_down_sync(0xFFFFFFFFu, ss, off);
        }
        if (lane == 0) part[k & 1][wid] = make_float2(s, ss);

        // Prefetch next row BEFORE the barrier: its DRAM latency hides under
        // the barrier + epilogue below.
        float4 nr0, nr1; int4 ni0, ni1;
        const long nbase = base + DIM;
        if (k + 1 < ROWS_PER_BLOCK) {
            nr0 = __ldcs(reinterpret_cast<const float4*>(res + nbase));
            nr1 = __ldcs(reinterpret_cast<const float4*>(res + nbase) + 1);
            ni0 = __ldcs(reinterpret_cast<const int4*>(qin + nbase));
            ni1 = __ldcs(reinterpret_cast<const int4*>(qin + nbase) + 1);
        }

        __syncthreads();

        // Redundant final sum of 16 warp partials (no second barrier needed:
        // buffer parity + the one barrier per row make reuse safe).
        s = 0.0f; ss = 0.0f;
        #pragma unroll
        for (int i = 0; i < NWARPS; ++i) {
            float2 p = part[k & 1][i];
            s += p.x; ss += p.y;
        }

        const float mean = s * inv_d;
        const float var  = fmaxf(ss * inv_d - mean * mean, 0.0f);
        const float rstd = rsqrtf(var + EPS);

        float qv[PER_THREAD];
        qv[0] = fminf(fmaxf(rintf(fmaf((v[0] - mean) * rstd, w0.x, b0.x)), -128.0f), 127.0f);
        qv[1] = fminf(fmaxf(rintf(fmaf((v[1] - mean) * rstd, w0.y, b0.y)), -128.0f), 127.0f);
        qv[2] = fminf(fmaxf(rintf(fmaf((v[2] - mean) * rstd, w0.z, b0.z)), -128.0f), 127.0f);
        qv[3] = fminf(fmaxf(rintf(fmaf((v[3] - mean) * rstd, w0.w, b0.w)), -128.0f), 127.0f);
        qv[4] = fminf(fmaxf(rintf(fmaf((v[4] - mean) * rstd, w1.x, b1.x)), -128.0f), 127.0f);
        qv[5] = fminf(fmaxf(rintf(fmaf((v[5] - mean) * rstd, w1.y, b1.y)), -128.0f), 127.0f);
        qv[6] = fminf(fmaxf(rintf(fmaf((v[6] - mean) * rstd, w1.z, b1.z)), -128.0f), 127.0f);
        qv[7] = fminf(fmaxf(rintf(fmaf((v[7] - mean) * rstd, w1.w, b1.w)), -128.0f), 127.0f);

        if (q_mode == 0) {
            __stcs(reinterpret_cast<float4*>(qf_out + base),
                   make_float4(qv[0], qv[1], qv[2], qv[3]));
            __stcs(reinterpret_cast<float4*>(qf_out + base) + 1,
                   make_float4(qv[4], qv[5], qv[6], qv[7]));
        } else {
            int8_t p8[8];
            #pragma unroll
            for (int j = 0; j < PER_THREAD; ++j) p8[j] = (int8_t)(int)qv[j];
            __stcs(reinterpret_cast<unsigned long long*>(q8_out + base),
                   *reinterpret_cast<const unsigned long long*>(p8));
        }

        // Rotate pipeline registers.
        r0 = nr0; r1 = nr1; i0 = ni0; i1 = ni1;
        base = nbase;
    }
}

extern "C" void kernel_launch(void* const* d_in, const int* in_sizes, int n_in,
                              void* d_out, int out_size) {
    const float* res  = (const float*)d_in[0];   // residual_input_fp [T, D] fp32
    const int*   qin  = (const int*)d_in[1];     // input_int32       [T, D] int32
    const float* w    = (const float*)d_in[2];   // weight [D] fp32
    const float* bias = (const float*)d_in[3];   // bias   [D] fp32

    const long TD = (long)TOKENS * DIM;

    float*  x_out  = (float*)d_out;
    float*  qf_out = nullptr;
    int8_t* q8_out = nullptr;
    int q_mode;

    if ((long)out_size == 5 * TD) {
        // int8/byte-packed output: x fp32 raw bytes first, then q int8
        q_mode = 1;
        q8_out = (int8_t*)d_out + 4 * TD;
    } else {
        // default: fp32 output, x then q (as float), each T*D elements
        q_mode = 0;
        qf_out = (float*)d_out + TD;
    }

    dq_add_ln_q_kernel<<<TOKENS / ROWS_PER_BLOCK, NTHREADS>>>(
        res, qin, w, bias, x_out, qf_out, q8_out, q_mode);
}